// round 1
// baseline (speedup 1.0000x reference)
#include <cuda_runtime.h>
#include <cstddef>

// Problem constants (fixed by the dataset)
#define EN    1000000
#define NN    100000
#define EORI  200000
#define DD    128
#define RR    32
#define HH    128
#define NRELC 200

#define L2E 1.4426950408889634f

// ---------------- scratch (device globals; no cudaMalloc allowed) -------------
__device__ float g_h[(size_t)EN * HH];   // 512 MB: pre-BN activations
__device__ float g_w[EN];                // edge logits, then exp values
__device__ float g_sum[HH];
__device__ float g_sumsq[HH];
__device__ float g_ginv[HH];
__device__ float g_shift[HH];
__device__ unsigned g_nmax[NN];          // encoded-float per-node max
__device__ float g_nsum[NN];             // per-node softmax denominator
__device__ unsigned char g_flag[EN];     // is-original-edge flag
__device__ float g_prec[NRELC * HH];     // rel_emb@W0[128:,:] + b0

// order-preserving float<->uint encoding for atomicMax
__device__ __forceinline__ unsigned encf(float f) {
    unsigned u = __float_as_uint(f);
    return (u & 0x80000000u) ? ~u : (u | 0x80000000u);
}
__device__ __forceinline__ float decf(unsigned u) {
    return __uint_as_float((u & 0x80000000u) ? (u & 0x7fffffffu) : ~u);
}

// ---------------- kernels ----------------------------------------------------

__global__ void k_init() {
    int i = blockIdx.x * blockDim.x + threadIdx.x;
    if (i < HH) { g_sum[i] = 0.f; g_sumsq[i] = 0.f; }
    if (i < NN) { g_nmax[i] = 0u; g_nsum[i] = 0.f; }
    if (i < EN) g_flag[i] = 0;
}

__global__ void k_flag(const int* __restrict__ ori) {
    int i = blockIdx.x * blockDim.x + threadIdx.x;
    if (i < EORI) g_flag[ori[i]] = 1;
}

// prec[r][c] = b0[c] + sum_k rel[r][k] * W0[128+k][c]
__global__ void k_prec(const float* __restrict__ rel,
                       const float* __restrict__ W0,
                       const float* __restrict__ b0) {
    int i = blockIdx.x * blockDim.x + threadIdx.x;
    if (i >= NRELC * HH) return;
    int r = i / HH, c = i % HH;
    float s = b0[c];
#pragma unroll
    for (int k = 0; k < RR; k++)
        s = fmaf(rel[r * RR + k], W0[(DD + k) * HH + c], s);
    g_prec[i] = s;
}

// Main pass: sim = exp(-|nf[row]-nf[col]|); h = sim @ W0[:128] + prec[etype]
// Stores h to g_h and accumulates per-channel sum / sumsq for BatchNorm.
// Tile: 64 edges x 128 channels, K=128, 256 threads (16x16, TM=4, TN=8).
__global__ __launch_bounds__(256) void k_pass1(
    const float* __restrict__ nf,
    const float* __restrict__ W0,
    const int* __restrict__ rowv,
    const int* __restrict__ colv,
    const int* __restrict__ etype) {
    extern __shared__ float sm[];
    float* As = sm;               // [128][68]   (k-major, padded)
    float* Bs = sm + 128 * 68;    // [128][128]  (k-major)

    const int tid = threadIdx.x;
    const int e0 = blockIdx.x * 64;

    // load W0 sim-part (first 128*128 floats, contiguous) into smem
    {
        const float4* src = (const float4*)W0;
        float4* dst = (float4*)Bs;
        for (int i = tid; i < 128 * 128 / 4; i += 256) dst[i] = src[i];
    }
    // fill As with sim values: 4 threads per edge, 32 dims each
    {
        int le = tid >> 2;
        int seg = tid & 3;
        int e = e0 + le;
        int rn = rowv[e], cn = colv[e];
        const float4* ra = (const float4*)(nf + (size_t)rn * DD + seg * 32);
        const float4* rb = (const float4*)(nf + (size_t)cn * DD + seg * 32);
#pragma unroll
        for (int i = 0; i < 8; i++) {
            float4 a = ra[i], b = rb[i];
            int k = seg * 32 + i * 4;
            As[(k + 0) * 68 + le] = exp2f(-L2E * fabsf(a.x - b.x));
            As[(k + 1) * 68 + le] = exp2f(-L2E * fabsf(a.y - b.y));
            As[(k + 2) * 68 + le] = exp2f(-L2E * fabsf(a.z - b.z));
            As[(k + 3) * 68 + le] = exp2f(-L2E * fabsf(a.w - b.w));
        }
    }
    __syncthreads();

    const int tx = tid & 15;   // channel group: channels tx*8 .. tx*8+7
    const int ty = tid >> 4;   // edge group:    edges   ty*4 .. ty*4+3

    float acc[4][8];
#pragma unroll
    for (int m = 0; m < 4; m++)
#pragma unroll
        for (int n = 0; n < 8; n++) acc[m][n] = 0.f;

    const float* ap = As + ty * 4;
    const float* bp = Bs + tx * 8;

#pragma unroll 8
    for (int k = 0; k < 128; k++) {
        float4 av = *(const float4*)(ap + k * 68);
        float4 bv0 = *(const float4*)(bp + k * 128);
        float4 bv1 = *(const float4*)(bp + k * 128 + 4);
        float am[4] = {av.x, av.y, av.z, av.w};
        float bn[8] = {bv0.x, bv0.y, bv0.z, bv0.w, bv1.x, bv1.y, bv1.z, bv1.w};
#pragma unroll
        for (int m = 0; m < 4; m++)
#pragma unroll
            for (int n = 0; n < 8; n++)
                acc[m][n] = fmaf(am[m], bn[n], acc[m][n]);
    }

    // epilogue: add rel/bias precomputed term, store h, accumulate stats
    float ps[8], pq[8];
#pragma unroll
    for (int n = 0; n < 8; n++) { ps[n] = 0.f; pq[n] = 0.f; }

#pragma unroll
    for (int m = 0; m < 4; m++) {
        int e = e0 + ty * 4 + m;
        int et = etype[e];
        const float4* pr = (const float4*)(g_prec + et * HH + tx * 8);
        float4 p0 = pr[0], p1 = pr[1];
        float hv[8];
        hv[0] = acc[m][0] + p0.x; hv[1] = acc[m][1] + p0.y;
        hv[2] = acc[m][2] + p0.z; hv[3] = acc[m][3] + p0.w;
        hv[4] = acc[m][4] + p1.x; hv[5] = acc[m][5] + p1.y;
        hv[6] = acc[m][6] + p1.z; hv[7] = acc[m][7] + p1.w;
        float4* outp = (float4*)(g_h + (size_t)e * HH + tx * 8);
        outp[0] = make_float4(hv[0], hv[1], hv[2], hv[3]);
        outp[1] = make_float4(hv[4], hv[5], hv[6], hv[7]);
#pragma unroll
        for (int n = 0; n < 8; n++) {
            ps[n] += hv[n];
            pq[n] = fmaf(hv[n], hv[n], pq[n]);
        }
    }

    // reduce stats: combine ty-pairs within warp, then across warps via smem
#pragma unroll
    for (int n = 0; n < 8; n++) {
        ps[n] += __shfl_xor_sync(0xffffffffu, ps[n], 16);
        pq[n] += __shfl_xor_sync(0xffffffffu, pq[n], 16);
    }
    __syncthreads();           // done reading As; reuse it
    float* redS = sm;          // [8][128]
    float* redQ = sm + 1024;   // [8][128]
    int lane = tid & 31, wrp = tid >> 5;
    if (lane < 16) {
#pragma unroll
        for (int n = 0; n < 8; n++) {
            redS[wrp * 128 + lane * 8 + n] = ps[n];
            redQ[wrp * 128 + lane * 8 + n] = pq[n];
        }
    }
    __syncthreads();
    if (tid < HH) {
        float s = 0.f, q = 0.f;
#pragma unroll
        for (int w2 = 0; w2 < 8; w2++) {
            s += redS[w2 * 128 + tid];
            q += redQ[w2 * 128 + tid];
        }
        atomicAdd(&g_sum[tid], s);
        atomicAdd(&g_sumsq[tid], q);
    }
}

__global__ void k_stats(const float* __restrict__ gamma,
                        const float* __restrict__ beta) {
    int c = threadIdx.x;
    if (c >= HH) return;
    float mu = g_sum[c] * (1.0f / EN);
    float var = g_sumsq[c] * (1.0f / EN) - mu * mu;
    float gi = gamma[c] * rsqrtf(var + 1e-5f);
    g_ginv[c] = gi;
    g_shift[c] = beta[c] - mu * gi;
}

// w = leaky(BN(h)) @ W1 + b1; ori blend; per-node max via atomicMax.
// One warp per edge (grid-stride).
__global__ __launch_bounds__(256) void k_pass3(const int* __restrict__ colv,
                                               const float* __restrict__ W1,
                                               const float* __restrict__ b1) {
    int lane = threadIdx.x & 31;
    int warp = (blockIdx.x * blockDim.x + threadIdx.x) >> 5;
    int nwarp = (gridDim.x * blockDim.x) >> 5;
    float4 gi = *(const float4*)(g_ginv + lane * 4);
    float4 sh = *(const float4*)(g_shift + lane * 4);
    float4 w1 = *(const float4*)(W1 + lane * 4);
    float b1v = b1[0];
    for (int e = warp; e < EN; e += nwarp) {
        float4 h = *(const float4*)(g_h + (size_t)e * HH + lane * 4);
        float t, l, s;
        t = fmaf(h.x, gi.x, sh.x); l = fmaxf(t, 0.f) + 0.01f * fminf(t, 0.f); s = l * w1.x;
        t = fmaf(h.y, gi.y, sh.y); l = fmaxf(t, 0.f) + 0.01f * fminf(t, 0.f); s = fmaf(l, w1.y, s);
        t = fmaf(h.z, gi.z, sh.z); l = fmaxf(t, 0.f) + 0.01f * fminf(t, 0.f); s = fmaf(l, w1.z, s);
        t = fmaf(h.w, gi.w, sh.w); l = fmaxf(t, 0.f) + 0.01f * fminf(t, 0.f); s = fmaf(l, w1.w, s);
        s += __shfl_xor_sync(0xffffffffu, s, 16);
        s += __shfl_xor_sync(0xffffffffu, s, 8);
        s += __shfl_xor_sync(0xffffffffu, s, 4);
        s += __shfl_xor_sync(0xffffffffu, s, 2);
        s += __shfl_xor_sync(0xffffffffu, s, 1);
        if (lane == 0) {
            float wv = s + b1v;
            if (g_flag[e]) wv = 0.5f * wv + 0.5f;
            g_w[e] = wv;
            atomicMax(&g_nmax[colv[e]], encf(wv));
        }
    }
}

__global__ void k_pass4(const int* __restrict__ colv) {
    int e = blockIdx.x * blockDim.x + threadIdx.x;
    if (e >= EN) return;
    float wv = g_w[e];
    int cn = colv[e];
    float m = decf(g_nmax[cn]);
    float ev = exp2f((wv - m) * L2E);
    g_w[e] = ev;
    atomicAdd(&g_nsum[cn], ev);
}

__global__ void k_pass5(const int* __restrict__ colv, float* __restrict__ out) {
    int e = blockIdx.x * blockDim.x + threadIdx.x;
    if (e >= EN) return;
    int cn = colv[e];
    float o = g_w[e] / g_nsum[cn];
    out[e] = (o > 1e-4f) ? o : 0.f;
}

// ---------------- launch ------------------------------------------------------
extern "C" void kernel_launch(void* const* d_in, const int* in_sizes, int n_in,
                              void* d_out, int out_size) {
    const float* n_feat  = (const float*)d_in[0];
    const float* rel_emb = (const float*)d_in[1];
    const float* W0      = (const float*)d_in[2];
    const float* b0      = (const float*)d_in[3];
    const float* gamma   = (const float*)d_in[4];
    const float* beta    = (const float*)d_in[5];
    const float* W1      = (const float*)d_in[6];
    const float* b1      = (const float*)d_in[7];
    const int*   rowv    = (const int*)d_in[8];
    const int*   colv    = (const int*)d_in[9];
    const int*   etype   = (const int*)d_in[10];
    const int*   ori     = (const int*)d_in[11];
    float* out = (float*)d_out;

    static bool attr_done = false;
    const int smem1 = (128 * 68 + 128 * 128) * (int)sizeof(float);  // 100352 B
    if (!attr_done) {
        cudaFuncSetAttribute(k_pass1, cudaFuncAttributeMaxDynamicSharedMemorySize, smem1);
        attr_done = true;
    }

    k_init<<<(EN + 255) / 256, 256>>>();
    k_flag<<<(EORI + 255) / 256, 256>>>(ori);
    k_prec<<<(NRELC * HH + 255) / 256, 256>>>(rel_emb, W0, b0);
    k_pass1<<<EN / 64, 256, smem1>>>(n_feat, W0, rowv, colv, etype);
    k_stats<<<1, 128>>>(gamma, beta);
    k_pass3<<<2048, 256>>>(colv, W1, b1);
    k_pass4<<<(EN + 255) / 256, 256>>>(colv);
    k_pass5<<<(EN + 255) / 256, 256>>>(colv, out);
}

// round 2
// speedup vs baseline: 1.4269x; 1.4269x over previous
#include <cuda_runtime.h>
#include <cstddef>

// Problem constants (fixed by the dataset)
#define EN    1000000
#define NN    100000
#define EORI  200000
#define DD    128
#define RR    32
#define HH    128
#define NRELC 200

#define L2E 1.4426950408889634f

#define TILE_E 256          // edges per block
#define AS_STRIDE 260       // 256 + 4 pad (floats)

// ---------------- scratch (device globals; no cudaMalloc allowed) -------------
__device__ float g_h[(size_t)EN * HH];   // 512 MB: pre-BN activations
__device__ float g_w[EN];                // edge logits, then exp values
__device__ float g_sum[HH];
__device__ float g_sumsq[HH];
__device__ float g_ginv[HH];
__device__ float g_shift[HH];
__device__ unsigned g_nmax[NN];          // encoded-float per-node max
__device__ float g_nsum[NN];             // per-node softmax denominator
__device__ unsigned char g_flag[EN];     // is-original-edge flag
__device__ float g_prec[NRELC * HH];     // rel_emb@W0[128:,:] + b0

// order-preserving float<->uint encoding for atomicMax
__device__ __forceinline__ unsigned encf(float f) {
    unsigned u = __float_as_uint(f);
    return (u & 0x80000000u) ? ~u : (u | 0x80000000u);
}
__device__ __forceinline__ float decf(unsigned u) {
    return __uint_as_float((u & 0x80000000u) ? (u & 0x7fffffffu) : ~u);
}

// ---------------- small kernels ----------------------------------------------

__global__ void k_init() {
    int i = blockIdx.x * blockDim.x + threadIdx.x;
    if (i < HH) { g_sum[i] = 0.f; g_sumsq[i] = 0.f; }
    if (i < NN) { g_nmax[i] = 0u; g_nsum[i] = 0.f; }
    if (i < EN) g_flag[i] = 0;
}

__global__ void k_flag(const int* __restrict__ ori) {
    int i = blockIdx.x * blockDim.x + threadIdx.x;
    if (i < EORI) g_flag[ori[i]] = 1;
}

// prec[r][c] = b0[c] + sum_k rel[r][k] * W0[128+k][c]
__global__ void k_prec(const float* __restrict__ rel,
                       const float* __restrict__ W0,
                       const float* __restrict__ b0) {
    int i = blockIdx.x * blockDim.x + threadIdx.x;
    if (i >= NRELC * HH) return;
    int r = i / HH, c = i % HH;
    float s = b0[c];
#pragma unroll
    for (int k = 0; k < RR; k++)
        s = fmaf(rel[r * RR + k], W0[(DD + k) * HH + c], s);
    g_prec[i] = s;
}

// ---------------- main GEMM pass ----------------------------------------------
// sim = exp(-|nf[row]-nf[col]|); h = sim @ W0[:128] + prec[etype]
// Tile: 256 edges x 128 channels, K=128. 512 threads, TM=8 (4+4), TN=8 (4+4).
__global__ __launch_bounds__(512) void k_pass1(
    const float* __restrict__ nf,
    const float* __restrict__ W0,
    const int* __restrict__ rowv,
    const int* __restrict__ colv,
    const int* __restrict__ etype) {
    extern __shared__ float sm[];
    float* As = sm;                              // [128][AS_STRIDE] k-major
    float* Bs = sm + 128 * AS_STRIDE;            // [128][128] k-major
    float* ssum = Bs + 128 * 128;                // [128]
    float* ssq  = ssum + 128;                    // [128]

    const int tid = threadIdx.x;
    const int e0 = blockIdx.x * TILE_E;

    if (tid < HH) { ssum[tid] = 0.f; ssq[tid] = 0.f; }

    // ---- fill Bs: W0 sim-part (first 128x128 floats, contiguous) ----
    {
        const float4* src = (const float4*)W0;
        float4* dst = (float4*)Bs;
#pragma unroll
        for (int i = 0; i < 8; i++) dst[tid + i * 512] = src[tid + i * 512];
    }
    // ---- fill As: 2 threads per edge, 64 dims each ----
    {
        const int le = tid >> 1;          // local edge 0..255
        const int seg = tid & 1;          // dim half
        const int e = e0 + le;
        if (e < EN) {
            const int rn = rowv[e], cn = colv[e];
            const float4* ra = (const float4*)(nf + (size_t)rn * DD + seg * 64);
            const float4* rb = (const float4*)(nf + (size_t)cn * DD + seg * 64);
#pragma unroll
            for (int i = 0; i < 16; i++) {
                float4 a = ra[i], b = rb[i];
                int k = seg * 64 + i * 4;
                As[(k + 0) * AS_STRIDE + le] = exp2f(-L2E * fabsf(a.x - b.x));
                As[(k + 1) * AS_STRIDE + le] = exp2f(-L2E * fabsf(a.y - b.y));
                As[(k + 2) * AS_STRIDE + le] = exp2f(-L2E * fabsf(a.z - b.z));
                As[(k + 3) * AS_STRIDE + le] = exp2f(-L2E * fabsf(a.w - b.w));
            }
        } else {
#pragma unroll
            for (int i = 0; i < 16; i++) {
                int k = seg * 64 + i * 4;
                As[(k + 0) * AS_STRIDE + le] = 0.f;
                As[(k + 1) * AS_STRIDE + le] = 0.f;
                As[(k + 2) * AS_STRIDE + le] = 0.f;
                As[(k + 3) * AS_STRIDE + le] = 0.f;
            }
        }
    }
    __syncthreads();

    const int tx = tid & 15;    // channel group
    const int ty = tid >> 4;    // edge group (0..31)
    const int ca = tx * 4;      // channels ca..ca+3 and 64+ca..64+ca+3
    const int ra = ty * 4;      // edges ra..ra+3 and 128+ra..128+ra+3

    float acc[2][4][8];
#pragma unroll
    for (int mi = 0; mi < 2; mi++)
#pragma unroll
        for (int mj = 0; mj < 4; mj++)
#pragma unroll
            for (int n = 0; n < 8; n++) acc[mi][mj][n] = 0.f;

    const float* ap = As + ra;
    const float* bp = Bs + ca;

#pragma unroll 4
    for (int k = 0; k < 128; k++) {
        float4 a0 = *(const float4*)(ap + k * AS_STRIDE);
        float4 a1 = *(const float4*)(ap + k * AS_STRIDE + 128);
        float4 b0 = *(const float4*)(bp + k * 128);
        float4 b1 = *(const float4*)(bp + k * 128 + 64);
        float am[2][4] = {{a0.x, a0.y, a0.z, a0.w}, {a1.x, a1.y, a1.z, a1.w}};
        float bn[8] = {b0.x, b0.y, b0.z, b0.w, b1.x, b1.y, b1.z, b1.w};
#pragma unroll
        for (int mi = 0; mi < 2; mi++)
#pragma unroll
            for (int mj = 0; mj < 4; mj++)
#pragma unroll
                for (int n = 0; n < 8; n++)
                    acc[mi][mj][n] = fmaf(am[mi][mj], bn[n], acc[mi][mj][n]);
    }

    // ---- epilogue: add prec, store h, accumulate BN stats ----
    float ps[8], pq[8];
#pragma unroll
    for (int n = 0; n < 8; n++) { ps[n] = 0.f; pq[n] = 0.f; }

#pragma unroll
    for (int mi = 0; mi < 2; mi++) {
#pragma unroll
        for (int mj = 0; mj < 4; mj++) {
            const int e = e0 + mi * 128 + ra + mj;
            if (e >= EN) continue;
            const int et = etype[e];
            const float4 p0 = *(const float4*)(g_prec + et * HH + ca);
            const float4 p1 = *(const float4*)(g_prec + et * HH + 64 + ca);
            float hv[8];
            hv[0] = acc[mi][mj][0] + p0.x; hv[1] = acc[mi][mj][1] + p0.y;
            hv[2] = acc[mi][mj][2] + p0.z; hv[3] = acc[mi][mj][3] + p0.w;
            hv[4] = acc[mi][mj][4] + p1.x; hv[5] = acc[mi][mj][5] + p1.y;
            hv[6] = acc[mi][mj][6] + p1.z; hv[7] = acc[mi][mj][7] + p1.w;
            *(float4*)(g_h + (size_t)e * HH + ca) =
                make_float4(hv[0], hv[1], hv[2], hv[3]);
            *(float4*)(g_h + (size_t)e * HH + 64 + ca) =
                make_float4(hv[4], hv[5], hv[6], hv[7]);
#pragma unroll
            for (int n = 0; n < 8; n++) {
                ps[n] += hv[n];
                pq[n] = fmaf(hv[n], hv[n], pq[n]);
            }
        }
    }
#pragma unroll
    for (int n = 0; n < 8; n++) {
        const int c = (n < 4) ? (ca + n) : (64 + ca + n - 4);
        atomicAdd(&ssum[c], ps[n]);
        atomicAdd(&ssq[c], pq[n]);
    }
    __syncthreads();
    if (tid < HH) {
        atomicAdd(&g_sum[tid], ssum[tid]);
        atomicAdd(&g_sumsq[tid], ssq[tid]);
    }
}

__global__ void k_stats(const float* __restrict__ gamma,
                        const float* __restrict__ beta) {
    int c = threadIdx.x;
    if (c >= HH) return;
    float mu = g_sum[c] * (1.0f / EN);
    float var = g_sumsq[c] * (1.0f / EN) - mu * mu;
    float gi = gamma[c] * rsqrtf(var + 1e-5f);
    g_ginv[c] = gi;
    g_shift[c] = beta[c] - mu * gi;
}

// w = leaky(BN(h)) @ W1 + b1; ori blend; per-node max via atomicMax.
__global__ __launch_bounds__(256) void k_pass3(const int* __restrict__ colv,
                                               const float* __restrict__ W1,
                                               const float* __restrict__ b1) {
    int lane = threadIdx.x & 31;
    int warp = (blockIdx.x * blockDim.x + threadIdx.x) >> 5;
    int nwarp = (gridDim.x * blockDim.x) >> 5;
    float4 gi = *(const float4*)(g_ginv + lane * 4);
    float4 sh = *(const float4*)(g_shift + lane * 4);
    float4 w1 = *(const float4*)(W1 + lane * 4);
    float b1v = b1[0];
    for (int e = warp; e < EN; e += nwarp) {
        float4 h = *(const float4*)(g_h + (size_t)e * HH + lane * 4);
        float t, l, s;
        t = fmaf(h.x, gi.x, sh.x); l = fmaxf(t, 0.f) + 0.01f * fminf(t, 0.f); s = l * w1.x;
        t = fmaf(h.y, gi.y, sh.y); l = fmaxf(t, 0.f) + 0.01f * fminf(t, 0.f); s = fmaf(l, w1.y, s);
        t = fmaf(h.z, gi.z, sh.z); l = fmaxf(t, 0.f) + 0.01f * fminf(t, 0.f); s = fmaf(l, w1.z, s);
        t = fmaf(h.w, gi.w, sh.w); l = fmaxf(t, 0.f) + 0.01f * fminf(t, 0.f); s = fmaf(l, w1.w, s);
        s += __shfl_xor_sync(0xffffffffu, s, 16);
        s += __shfl_xor_sync(0xffffffffu, s, 8);
        s += __shfl_xor_sync(0xffffffffu, s, 4);
        s += __shfl_xor_sync(0xffffffffu, s, 2);
        s += __shfl_xor_sync(0xffffffffu, s, 1);
        if (lane == 0) {
            float wv = s + b1v;
            if (g_flag[e]) wv = 0.5f * wv + 0.5f;
            g_w[e] = wv;
            atomicMax(&g_nmax[colv[e]], encf(wv));
        }
    }
}

__global__ void k_pass4(const int* __restrict__ colv) {
    int e = blockIdx.x * blockDim.x + threadIdx.x;
    if (e >= EN) return;
    float wv = g_w[e];
    int cn = colv[e];
    float m = decf(g_nmax[cn]);
    float ev = exp2f((wv - m) * L2E);
    g_w[e] = ev;
    atomicAdd(&g_nsum[cn], ev);
}

__global__ void k_pass5(const int* __restrict__ colv, float* __restrict__ out) {
    int e = blockIdx.x * blockDim.x + threadIdx.x;
    if (e >= EN) return;
    int cn = colv[e];
    float o = g_w[e] / g_nsum[cn];
    out[e] = (o > 1e-4f) ? o : 0.f;
}

// ---------------- launch ------------------------------------------------------
extern "C" void kernel_launch(void* const* d_in, const int* in_sizes, int n_in,
                              void* d_out, int out_size) {
    const float* n_feat  = (const float*)d_in[0];
    const float* rel_emb = (const float*)d_in[1];
    const float* W0      = (const float*)d_in[2];
    const float* b0      = (const float*)d_in[3];
    const float* gamma   = (const float*)d_in[4];
    const float* beta    = (const float*)d_in[5];
    const float* W1      = (const float*)d_in[6];
    const float* b1      = (const float*)d_in[7];
    const int*   rowv    = (const int*)d_in[8];
    const int*   colv    = (const int*)d_in[9];
    const int*   etype   = (const int*)d_in[10];
    const int*   ori     = (const int*)d_in[11];
    float* out = (float*)d_out;

    static bool attr_done = false;
    const int smem1 = (128 * AS_STRIDE + 128 * 128 + 256) * (int)sizeof(float); // ~199.7 KB
    if (!attr_done) {
        cudaFuncSetAttribute(k_pass1, cudaFuncAttributeMaxDynamicSharedMemorySize, smem1);
        attr_done = true;
    }

    k_init<<<(EN + 255) / 256, 256>>>();
    k_flag<<<(EORI + 255) / 256, 256>>>(ori);
    k_prec<<<(NRELC * HH + 255) / 256, 256>>>(rel_emb, W0, b0);
    k_pass1<<<(EN + TILE_E - 1) / TILE_E, 512, smem1>>>(n_feat, W0, rowv, colv, etype);
    k_stats<<<1, 128>>>(gamma, beta);
    k_pass3<<<2048, 256>>>(colv, W1, b1);
    k_pass4<<<(EN + 255) / 256, 256>>>(colv);
    k_pass5<<<(EN + 255) / 256, 256>>>(colv, out);
}

// round 4
// speedup vs baseline: 1.7165x; 1.2030x over previous
#include <cuda_runtime.h>
#include <cstdint>
#include <cstddef>

// Problem constants
#define EN    1000000
#define NN    100000
#define EORI  200000
#define DD    128
#define RR    32
#define HH    128
#define NRELC 200
#define L2E   1.4426950408889634f

#define NT    7813          // ceil(EN/128)
#define GRID1 148

#define AS_STRIDE 132       // floats; conflict-free A-fragment LDS
#define BS_STRIDE 136       // floats; conflict-free B-fragment LDS

// ---------------- scratch globals ----------------
__device__ float g_h[(size_t)EN * HH];   // 512 MB pre-BN activations
__device__ float g_w[EN];
__device__ float g_sum[HH];
__device__ float g_sumsq[HH];
__device__ float g_ginv[HH];
__device__ float g_shift[HH];
__device__ unsigned g_nmax[NN];
__device__ float g_nsum[NN];
__device__ unsigned char g_flag[EN];
__device__ float g_prec[NRELC * HH];

// ---------------- helpers ----------------
__device__ __forceinline__ uint32_t tf32u(float x) {
    uint32_t o; asm("cvt.rna.tf32.f32 %0, %1;" : "=r"(o) : "f"(x)); return o;
}
__device__ __forceinline__ void mma_tf32(float c[4], const uint32_t a[4],
                                         const uint32_t b[2]) {
    asm volatile(
        "mma.sync.aligned.m16n8k8.row.col.f32.tf32.tf32.f32 "
        "{%0,%1,%2,%3}, {%4,%5,%6,%7}, {%8,%9}, {%0,%1,%2,%3};"
        : "+f"(c[0]), "+f"(c[1]), "+f"(c[2]), "+f"(c[3])
        : "r"(a[0]), "r"(a[1]), "r"(a[2]), "r"(a[3]), "r"(b[0]), "r"(b[1]));
}

__device__ __forceinline__ unsigned encf(float f) {
    unsigned u = __float_as_uint(f);
    return (u & 0x80000000u) ? ~u : (u | 0x80000000u);
}
__device__ __forceinline__ float decf(unsigned u) {
    return __uint_as_float((u & 0x80000000u) ? (u & 0x7fffffffu) : ~u);
}

// ---------------- small kernels ----------------
__global__ void k_init() {
    int i = blockIdx.x * blockDim.x + threadIdx.x;
    if (i < HH) { g_sum[i] = 0.f; g_sumsq[i] = 0.f; }
    if (i < NN) { g_nmax[i] = 0u; g_nsum[i] = 0.f; }
    if (i < EN) g_flag[i] = 0;
}
__global__ void k_flag(const int* __restrict__ ori) {
    int i = blockIdx.x * blockDim.x + threadIdx.x;
    if (i < EORI) g_flag[ori[i]] = 1;
}
__global__ void k_prec(const float* __restrict__ rel,
                       const float* __restrict__ W0,
                       const float* __restrict__ b0) {
    int i = blockIdx.x * blockDim.x + threadIdx.x;
    if (i >= NRELC * HH) return;
    int r = i / HH, c = i % HH;
    float s = b0[c];
#pragma unroll
    for (int k = 0; k < RR; k++)
        s = fmaf(rel[r * RR + k], W0[(DD + k) * HH + c], s);
    g_prec[i] = s;
}

// ---------------- pass1: sim + tf32 mma.sync GEMM + BN stats ------------------
// Persistent: 148 blocks x 256 threads. Tile = 128 edges x 128 ch, K = 128.
// Warp grid 4(m) x 2(n); warp tile 32 x 64 via m16n8k8 tf32.
__global__ __launch_bounds__(256, 1) void k_pass1(
    const float* __restrict__ nf,
    const float* __restrict__ W0,
    const int* __restrict__ rowv,
    const int* __restrict__ colv,
    const int* __restrict__ etype) {
    extern __shared__ uint32_t sm[];
    uint32_t* As = sm;                         // [128][AS_STRIDE] tf32 bits
    uint32_t* Bs = sm + 128 * AS_STRIDE;       // [128][BS_STRIDE] tf32 bits
    float* ssum = (float*)(Bs + 128 * BS_STRIDE);
    float* ssq  = ssum + 128;

    const int tid = threadIdx.x;
    const int wid = tid >> 5, lane = tid & 31;
    const int gid = lane >> 2, tg = lane & 3;
    const int wm = wid >> 1, wn = wid & 1;
    const int m0 = wm * 32, n0 = wn * 64;

    // load B = W0[:128,:] as tf32 bits, k-major rows
    for (int i = tid; i < 128 * 128; i += 256) {
        int k = i >> 7, n = i & 127;
        Bs[k * BS_STRIDE + n] = tf32u(W0[i]);
    }
    if (tid < HH) { ssum[tid] = 0.f; ssq[tid] = 0.f; }

    // per-thread BN stat accumulators; columns fixed per thread:
    // col(nt, half) = n0 + nt*8 + tg*2 + half
    float ps[16], pq[16];
#pragma unroll
    for (int i = 0; i < 16; i++) { ps[i] = 0.f; pq[i] = 0.f; }

    const int le = tid >> 1, seg = tid & 1;

    for (int tile = blockIdx.x; tile < NT; tile += GRID1) {
        // ---- produce sim tile (tf32) into As ----
        {
            const int e = tile * 128 + le;
            uint32_t* arow = As + le * AS_STRIDE + seg * 64;
            if (e < EN) {
                const int rn = rowv[e], cn = colv[e];
                const float4* ra = (const float4*)(nf + (size_t)rn * DD) + seg * 16;
                const float4* rb = (const float4*)(nf + (size_t)cn * DD) + seg * 16;
#pragma unroll
                for (int j = 0; j < 16; j++) {
                    float4 a = ra[j], b = rb[j];
                    uint4 s;
                    s.x = tf32u(exp2f(-L2E * fabsf(a.x - b.x)));
                    s.y = tf32u(exp2f(-L2E * fabsf(a.y - b.y)));
                    s.z = tf32u(exp2f(-L2E * fabsf(a.z - b.z)));
                    s.w = tf32u(exp2f(-L2E * fabsf(a.w - b.w)));
                    *(uint4*)(arow + j * 4) = s;
                }
            } else {
#pragma unroll
                for (int j = 0; j < 16; j++)
                    *(uint4*)(arow + j * 4) = make_uint4(0u, 0u, 0u, 0u);
            }
        }
        __syncthreads();

        // ---- warp MMA: 2 m-tiles x 8 n-tiles x 16 k-tiles ----
        float acc[2][8][4];
#pragma unroll
        for (int mt = 0; mt < 2; mt++)
#pragma unroll
            for (int nt = 0; nt < 8; nt++)
#pragma unroll
                for (int r = 0; r < 4; r++) acc[mt][nt][r] = 0.f;

#pragma unroll
        for (int kt = 0; kt < 16; kt++) {
            const int k0 = kt * 8;
            uint32_t afr[2][4];
#pragma unroll
            for (int mt = 0; mt < 2; mt++) {
                const uint32_t* ab =
                    As + (m0 + mt * 16 + gid) * AS_STRIDE + k0 + tg;
                afr[mt][0] = ab[0];
                afr[mt][1] = ab[8 * AS_STRIDE];
                afr[mt][2] = ab[4];
                afr[mt][3] = ab[8 * AS_STRIDE + 4];
            }
            uint32_t bfr[8][2];
#pragma unroll
            for (int nt = 0; nt < 8; nt++) {
                const uint32_t* bb =
                    Bs + (k0 + tg) * BS_STRIDE + n0 + nt * 8 + gid;
                bfr[nt][0] = bb[0];
                bfr[nt][1] = bb[4 * BS_STRIDE];
            }
#pragma unroll
            for (int mt = 0; mt < 2; mt++)
#pragma unroll
                for (int nt = 0; nt < 8; nt++)
                    mma_tf32(acc[mt][nt], afr[mt], bfr[nt]);
        }
        __syncthreads();   // As free for next iteration's produce

        // ---- epilogue: + prec[etype], store g_h, accumulate stats ----
#pragma unroll
        for (int mt = 0; mt < 2; mt++) {
#pragma unroll
            for (int rr = 0; rr < 2; rr++) {
                const int row = m0 + mt * 16 + rr * 8 + gid;
                const int e = tile * 128 + row;
                if (e < EN) {
                    const int et = etype[e];
                    const float2* prow = (const float2*)(g_prec + et * HH);
                    float2* hrow = (float2*)(g_h + (size_t)e * HH);
#pragma unroll
                    for (int nt = 0; nt < 8; nt++) {
                        const int c2i = (n0 + nt * 8 + tg * 2) >> 1;
                        float2 p = prow[c2i];
                        float v0 = acc[mt][nt][rr * 2 + 0] + p.x;
                        float v1 = acc[mt][nt][rr * 2 + 1] + p.y;
                        hrow[c2i] = make_float2(v0, v1);
                        ps[nt * 2 + 0] += v0; pq[nt * 2 + 0] = fmaf(v0, v0, pq[nt * 2 + 0]);
                        ps[nt * 2 + 1] += v1; pq[nt * 2 + 1] = fmaf(v1, v1, pq[nt * 2 + 1]);
                    }
                }
            }
        }
    }

    // ---- final BN stat reduction: regs -> smem -> global ----
    __syncthreads();
#pragma unroll
    for (int nt = 0; nt < 8; nt++) {
#pragma unroll
        for (int h = 0; h < 2; h++) {
            const int col = n0 + nt * 8 + tg * 2 + h;
            atomicAdd(&ssum[col], ps[nt * 2 + h]);
            atomicAdd(&ssq[col], pq[nt * 2 + h]);
        }
    }
    __syncthreads();
    if (tid < HH) {
        atomicAdd(&g_sum[tid], ssum[tid]);
        atomicAdd(&g_sumsq[tid], ssq[tid]);
    }
}

// ---------------- BN params ----------------
__global__ void k_stats(const float* __restrict__ gamma,
                        const float* __restrict__ beta) {
    int c = threadIdx.x;
    if (c >= HH) return;
    float mu = g_sum[c] * (1.0f / EN);
    float var = g_sumsq[c] * (1.0f / EN) - mu * mu;
    float gi = gamma[c] * rsqrtf(var + 1e-5f);
    g_ginv[c] = gi;
    g_shift[c] = beta[c] - mu * gi;
}

// ---------------- pass3: w = leaky(BN(h))@W1 + b1, blend, node max ------------
__global__ __launch_bounds__(256) void k_pass3(const int* __restrict__ colv,
                                               const float* __restrict__ W1,
                                               const float* __restrict__ b1) {
    int lane = threadIdx.x & 31;
    int warp = (blockIdx.x * blockDim.x + threadIdx.x) >> 5;
    int nwarp = (gridDim.x * blockDim.x) >> 5;
    float4 gi = *(const float4*)(g_ginv + lane * 4);
    float4 sh = *(const float4*)(g_shift + lane * 4);
    float4 w1 = *(const float4*)(W1 + lane * 4);
    float b1v = b1[0];
    for (int e = warp; e < EN; e += nwarp) {
        float4 h = *(const float4*)(g_h + (size_t)e * HH + lane * 4);
        float t, l, s;
        t = fmaf(h.x, gi.x, sh.x); l = fmaxf(t, 0.f) + 0.01f * fminf(t, 0.f); s = l * w1.x;
        t = fmaf(h.y, gi.y, sh.y); l = fmaxf(t, 0.f) + 0.01f * fminf(t, 0.f); s = fmaf(l, w1.y, s);
        t = fmaf(h.z, gi.z, sh.z); l = fmaxf(t, 0.f) + 0.01f * fminf(t, 0.f); s = fmaf(l, w1.z, s);
        t = fmaf(h.w, gi.w, sh.w); l = fmaxf(t, 0.f) + 0.01f * fminf(t, 0.f); s = fmaf(l, w1.w, s);
        s += __shfl_xor_sync(0xffffffffu, s, 16);
        s += __shfl_xor_sync(0xffffffffu, s, 8);
        s += __shfl_xor_sync(0xffffffffu, s, 4);
        s += __shfl_xor_sync(0xffffffffu, s, 2);
        s += __shfl_xor_sync(0xffffffffu, s, 1);
        if (lane == 0) {
            float wv = s + b1v;
            if (g_flag[e]) wv = 0.5f * wv + 0.5f;
            g_w[e] = wv;
            atomicMax(&g_nmax[colv[e]], encf(wv));
        }
    }
}

__global__ void k_pass4(const int* __restrict__ colv) {
    int e = blockIdx.x * blockDim.x + threadIdx.x;
    if (e >= EN) return;
    float wv = g_w[e];
    int cn = colv[e];
    float m = decf(g_nmax[cn]);
    float ev = exp2f((wv - m) * L2E);
    g_w[e] = ev;
    atomicAdd(&g_nsum[cn], ev);
}

__global__ void k_pass5(const int* __restrict__ colv, float* __restrict__ out) {
    int e = blockIdx.x * blockDim.x + threadIdx.x;
    if (e >= EN) return;
    int cn = colv[e];
    float o = g_w[e] / g_nsum[cn];
    out[e] = (o > 1e-4f) ? o : 0.f;
}

// ---------------- launch ----------------
extern "C" void kernel_launch(void* const* d_in, const int* in_sizes, int n_in,
                              void* d_out, int out_size) {
    const float* n_feat  = (const float*)d_in[0];
    const float* rel_emb = (const float*)d_in[1];
    const float* W0      = (const float*)d_in[2];
    const float* b0      = (const float*)d_in[3];
    const float* gamma   = (const float*)d_in[4];
    const float* beta    = (const float*)d_in[5];
    const float* W1      = (const float*)d_in[6];
    const float* b1      = (const float*)d_in[7];
    const int*   rowv    = (const int*)d_in[8];
    const int*   colv    = (const int*)d_in[9];
    const int*   etype   = (const int*)d_in[10];
    const int*   ori     = (const int*)d_in[11];
    float* out = (float*)d_out;

    const int smem1 = (128 * AS_STRIDE + 128 * BS_STRIDE + 256) * 4; // 138,240 B
    static bool attr_done = false;
    if (!attr_done) {
        cudaFuncSetAttribute(k_pass1, cudaFuncAttributeMaxDynamicSharedMemorySize, smem1);
        attr_done = true;
    }

    k_init<<<(EN + 255) / 256, 256>>>();
    k_flag<<<(EORI + 255) / 256, 256>>>(ori);
    k_prec<<<(NRELC * HH + 255) / 256, 256>>>(rel_emb, W0, b0);
    k_pass1<<<GRID1, 256, smem1>>>(n_feat, W0, rowv, colv, etype);
    k_stats<<<1, 128>>>(gamma, beta);
    k_pass3<<<2048, 256>>>(colv, W1, b1);
    k_pass4<<<(EN + 255) / 256, 256>>>(colv);
    k_pass5<<<(EN + 255) / 256, 256>>>(colv, out);
}